// round 5
// baseline (speedup 1.0000x reference)
#include <cuda_runtime.h>

// SymLoss: B=32, Flow/Mask (B,2,512,512) f32, A/B axes (B,2) f32.
// loss = (1/B) * sum_b num_b / denom_b
//   num_b = sum_{c,y,x} mask[c] * ((dphi1*b0 - dphi0*b1)^2) * valid
//   dphi  = flow - bilinear(flow shifted by (dy,dx))
//
// R5: block = 8 full rows. The 9 shifted flow rows (x-extended with clamped
// +/-16 guard) are staged in SMEM once; bilinear windows + (mostly) center
// reads become conflict-free LDS.128. Only mask reads stay in GMEM in-loop.

#define HH 512
#define WW 512
#define BN 32
#define GUARD 16
#define ROWF (WW + 2 * GUARD)   // 544 floats per staged row
#define NROWS 9

__global__ void sym_zero_out(float* out) { out[0] = 0.0f; }

// Read aligned 8-float window from a staged SMEM row, extract 5 used floats.
template <int O>
__device__ __forceinline__ void ldswin(const float* __restrict__ srow,
                                       int gxb, bool safe, float* w)
{
    if (safe) {
        const float4 a = *reinterpret_cast<const float4*>(srow + GUARD + gxb);
        const float4 b = *reinterpret_cast<const float4*>(srow + GUARD + gxb + 4);
        const float w8[8] = {a.x, a.y, a.z, a.w, b.x, b.y, b.z, b.w};
        #pragma unroll
        for (int i = 0; i < 5; i++) w[i] = w8[O + i];
    } else {
        #pragma unroll
        for (int i = 0; i < 5; i++) {
            const int gx = min(max(gxb + O + i, 0), WW - 1);
            w[i] = srow[GUARD + gx];
        }
    }
}

template <int O>
__device__ __forceinline__ float sym_body(
    const float (*sF)[NROWS][ROWF],
    const float* __restrict__ f0, const float* __restrict__ f1,
    const float* __restrict__ m0p, const float* __restrict__ m1p,
    int row0, int y0, int x0, int gxb, bool safe,
    int iy1, int hp, int x_lo, int x_hi,
    float w11, float w12, float w21, float w22, float sb0, float sb1)
{
    float xm[4];
    #pragma unroll
    for (int j = 0; j < 4; j++) {
        const int xx = x0 + j;
        xm[j] = (xx >= x_lo && xx < x_hi) ? 1.0f : 0.0f;
    }

    float acc[4] = {0.0f, 0.0f, 0.0f, 0.0f};

    const int slot0 = y0 - row0;              // 0 or 4
    float t0[5], t1[5], u0[5], u1[5];
    ldswin<O>(sF[0][slot0], gxb, safe, t0);
    ldswin<O>(sF[1][slot0], gxb, safe, t1);

    #pragma unroll
    for (int r = 0; r < 4; r++) {
        const int y     = y0 + r;
        const int slot  = slot0 + r + 1;      // row y+iy1+1 lives here
        const int cslot = slot0 + r - iy1;    // row y, if >= 0

        // masks: the only in-loop GMEM stream (independent -> batched)
        const float4 q0 = __ldg(reinterpret_cast<const float4*>(m0p + y * WW + x0));
        const float4 q1 = __ldg(reinterpret_cast<const float4*>(m1p + y * WW + x0));

        ldswin<O>(sF[0][slot], gxb, safe, u0);
        ldswin<O>(sF[1][slot], gxb, safe, u1);

        float4 c0, c1;
        if (cslot >= 0) {                     // warp-uniform
            c0 = *reinterpret_cast<const float4*>(&sF[0][cslot][GUARD + x0]);
            c1 = *reinterpret_cast<const float4*>(&sF[1][cslot][GUARD + x0]);
        } else {
            c0 = __ldg(reinterpret_cast<const float4*>(f0 + y * WW + x0));
            c1 = __ldg(reinterpret_cast<const float4*>(f1 + y * WW + x0));
        }

        const float yv = (y < hp) ? 1.0f : 0.0f;
        const float mm[4]  = {(q0.x + q1.x) * xm[0] * yv, (q0.y + q1.y) * xm[1] * yv,
                              (q0.z + q1.z) * xm[2] * yv, (q0.w + q1.w) * xm[3] * yv};
        const float c0a[4] = {c0.x, c0.y, c0.z, c0.w};
        const float c1a[4] = {c1.x, c1.y, c1.z, c1.w};

        #pragma unroll
        for (int j = 0; j < 4; j++) {
            const float ph0 = w11 * t0[j] + w12 * t0[j + 1]
                            + w21 * u0[j] + w22 * u0[j + 1];
            const float ph1 = w11 * t1[j] + w12 * t1[j + 1]
                            + w21 * u1[j] + w22 * u1[j + 1];
            const float d0 = c0a[j] - ph0;
            const float d1 = c1a[j] - ph1;
            const float s  = d1 * sb0 - d0 * sb1;
            acc[j] = fmaf(mm[j] * s, s, acc[j]);
        }

        #pragma unroll
        for (int i = 0; i < 5; i++) { t0[i] = u0[i]; t1[i] = u1[i]; }
    }
    return (acc[0] + acc[1]) + (acc[2] + acc[3]);
}

__global__ __launch_bounds__(256, 5) void symloss_kernel(
    const float* __restrict__ Flow,
    const float* __restrict__ Asym,
    const float* __restrict__ Bsym,
    const float* __restrict__ Mask,
    float* __restrict__ out)
{
    __shared__ float sF[2][NROWS][ROWF];      // 39168 B
    __shared__ float sred[8];

    const int b    = blockIdx.y;
    const int row0 = blockIdx.x * 8;

    const float a0  = __ldg(Asym + 2 * b);
    const float a1  = __ldg(Asym + 2 * b + 1);
    const float sb0 = __ldg(Bsym + 2 * b);
    const float sb1 = __ldg(Bsym + 2 * b + 1);

    const float dxf = -3.0f * a0;
    const float dyf = fabsf(3.0f * a1);
    const float dy1 = floorf(dyf);
    const float dx1 = floorf(dxf);
    const float fy  = dyf - dy1;
    const float fx  = dxf - dx1;
    const int   iy1 = (int)dy1;          // >= 0
    const int   ix1 = (int)dx1;          // may be negative

    const int hp   = HH - 1 - iy1;
    const int x_lo = max(0, -ix1);
    const int x_hi = min(WW, WW - 1 - ix1);

    const float w11 = (1.0f - fx) * (1.0f - fy);
    const float w12 = fx * (1.0f - fy);
    const float w21 = (1.0f - fx) * fy;
    const float w22 = fx * fy;

    const float* f0  = Flow + (size_t)b * 2 * HH * WW;
    const float* f1  = f0 + HH * WW;
    const float* m0p = Mask + (size_t)b * 2 * HH * WW;
    const float* m1p = m0p + HH * WW;

    // ---- stage 9 shifted rows x 2 channels into SMEM (x-guard clamped) ----
    #pragma unroll 1
    for (int i = threadIdx.x; i < 2 * NROWS * (ROWF / 4); i += 256) {
        const int ch  = i / (NROWS * (ROWF / 4));
        const int rem = i - ch * (NROWS * (ROWF / 4));
        const int rr  = rem / (ROWF / 4);
        const int xi  = rem - rr * (ROWF / 4);
        const int gy  = min(row0 + iy1 + rr, HH - 1);
        const float* rowp = (ch ? f1 : f0) + gy * WW;
        const int gx = xi * 4 - GUARD;
        float4 v;
        if (gx >= 0 && gx + 4 <= WW) {
            v = __ldg(reinterpret_cast<const float4*>(rowp + gx));
        } else {
            v.x = __ldg(rowp + min(max(gx + 0, 0), WW - 1));
            v.y = __ldg(rowp + min(max(gx + 1, 0), WW - 1));
            v.z = __ldg(rowp + min(max(gx + 2, 0), WW - 1));
            v.w = __ldg(rowp + min(max(gx + 3, 0), WW - 1));
        }
        *reinterpret_cast<float4*>(&sF[ch][rr][xi * 4]) = v;
    }
    __syncthreads();

    // 128 x-groups (4 px) x 2 y-halves; each thread walks 4 consecutive rows
    const int x0 = (threadIdx.x & 127) * 4;
    const int y0 = row0 + (threadIdx.x >> 7) * 4;

    const int  o    = ix1 & 3;                 // block-uniform misalignment
    const int  gxb  = x0 + (ix1 & ~3);         // 16B-aligned window base
    const int  oxb  = ix1 & ~3;
    const bool safe = (oxb >= -GUARD) && (oxb <= GUARD - 4); // uniform: guard covers

    float acc;
    switch (o) {                               // block-uniform branch
    case 0: acc = sym_body<0>(sF, f0, f1, m0p, m1p, row0, y0, x0, gxb, safe,
                              iy1, hp, x_lo, x_hi, w11, w12, w21, w22, sb0, sb1); break;
    case 1: acc = sym_body<1>(sF, f0, f1, m0p, m1p, row0, y0, x0, gxb, safe,
                              iy1, hp, x_lo, x_hi, w11, w12, w21, w22, sb0, sb1); break;
    case 2: acc = sym_body<2>(sF, f0, f1, m0p, m1p, row0, y0, x0, gxb, safe,
                              iy1, hp, x_lo, x_hi, w11, w12, w21, w22, sb0, sb1); break;
    default: acc = sym_body<3>(sF, f0, f1, m0p, m1p, row0, y0, x0, gxb, safe,
                              iy1, hp, x_lo, x_hi, w11, w12, w21, w22, sb0, sb1); break;
    }

    // ---- reduction: warp shuffle -> shared -> one atomic per block ----
    #pragma unroll
    for (int off = 16; off; off >>= 1)
        acc += __shfl_xor_sync(0xffffffffu, acc, off);

    const int wid = threadIdx.x >> 5;
    const int lid = threadIdx.x & 31;
    if (lid == 0) sred[wid] = acc;
    __syncthreads();

    if (threadIdx.x == 0) {
        float s = 0.0f;
        #pragma unroll
        for (int i = 0; i < 8; i++) s += sred[i];
        const float denom = 2.0f * (float)max(hp, 1)
                          * (float)max(x_hi - x_lo, 1) * (float)BN;
        atomicAdd(out, s / denom);
    }
}

extern "C" void kernel_launch(void* const* d_in, const int* in_sizes, int n_in,
                              void* d_out, int out_size)
{
    const float* Flow = (const float*)d_in[0];
    const float* Asym = (const float*)d_in[1];
    const float* Bsym = (const float*)d_in[2];
    const float* Mask = (const float*)d_in[3];
    float* out = (float*)d_out;

    sym_zero_out<<<1, 1>>>(out);
    dim3 grid(HH / 8, BN);
    symloss_kernel<<<grid, 256>>>(Flow, Asym, Bsym, Mask, out);
}

// round 6
// speedup vs baseline: 1.0500x; 1.0500x over previous
#include <cuda_runtime.h>

// SymLoss: B=32, Flow/Mask (B,2,512,512) f32, A/B axes (B,2) f32.
// loss = (1/B) * sum_b num_b / denom_b
//   num_b = sum_{c,y,x} mask[c] * ((dphi1*b0 - dphi0*b1)^2) * valid
//   dphi  = flow - bilinear(flow shifted by (dy,dx))
//
// R6: R4 structure minus rolling-window state. Channels processed
// sequentially per row; all loads per row independent (re-load window rows,
// they are L2 hits). Lower liveness -> 40 regs -> 6 blocks/SM for more
// warps x in-flight loads (kernel is latency-bound, nothing saturated).

#define HH 512
#define WW 512
#define BN 32

__global__ void sym_zero_out(float* out) { out[0] = 0.0f; }

// Load the aligned 8-float window, keep only the 5 consumed floats [O..O+4].
template <int O>
__device__ __forceinline__ void loadwin(const float* __restrict__ rowp,
                                        int gxb, bool safe, float* w)
{
    if (safe) {
        const float4 a = __ldg(reinterpret_cast<const float4*>(rowp + gxb));
        const float4 b = __ldg(reinterpret_cast<const float4*>(rowp + gxb + 4));
        const float w8[8] = {a.x, a.y, a.z, a.w, b.x, b.y, b.z, b.w};
        #pragma unroll
        for (int i = 0; i < 5; i++) w[i] = w8[O + i];
    } else {
        #pragma unroll
        for (int i = 0; i < 5; i++) {
            const int gx = min(max(gxb + O + i, 0), WW - 1);
            w[i] = __ldg(rowp + gx);
        }
    }
}

template <int O>
__device__ __forceinline__ float sym_body(
    const float* __restrict__ f0, const float* __restrict__ f1,
    const float* __restrict__ m0p, const float* __restrict__ m1p,
    int y0, int x0, int gxb, bool safe,
    int iy1, int hp, int x_lo, int x_hi,
    float w11, float w12, float w21, float w22, float sb0, float sb1)
{
    // x-validity is row-independent.
    float xm[4];
    #pragma unroll
    for (int j = 0; j < 4; j++) {
        const int xx = x0 + j;
        xm[j] = (xx >= x_lo && xx < x_hi) ? 1.0f : 0.0f;
    }

    float acc[4] = {0.0f, 0.0f, 0.0f, 0.0f};

    #pragma unroll
    for (int r = 0; r < 4; r++) {
        const int y   = y0 + r;
        const int gy1 = min(y + iy1, HH - 1);
        const int gy2 = min(y + iy1 + 1, HH - 1);
        const float yv = (y < hp) ? 1.0f : 0.0f;

        // independent GMEM streams for this row
        const float4 q0 = __ldg(reinterpret_cast<const float4*>(m0p + y * WW + x0));
        const float4 q1 = __ldg(reinterpret_cast<const float4*>(m1p + y * WW + x0));
        const float4 c0 = __ldg(reinterpret_cast<const float4*>(f0  + y * WW + x0));
        const float4 c1 = __ldg(reinterpret_cast<const float4*>(f1  + y * WW + x0));

        const float mm[4]  = {(q0.x + q1.x) * xm[0] * yv, (q0.y + q1.y) * xm[1] * yv,
                              (q0.z + q1.z) * xm[2] * yv, (q0.w + q1.w) * xm[3] * yv};
        const float c0a[4] = {c0.x, c0.y, c0.z, c0.w};
        const float c1a[4] = {c1.x, c1.y, c1.z, c1.w};

        float t[5], u[5];

        // ---- channel 0 ----
        loadwin<O>(f0 + gy1 * WW, gxb, safe, t);
        loadwin<O>(f0 + gy2 * WW, gxb, safe, u);
        float d0[4];
        #pragma unroll
        for (int j = 0; j < 4; j++) {
            const float ph = w11 * t[j] + w12 * t[j + 1]
                           + w21 * u[j] + w22 * u[j + 1];
            d0[j] = c0a[j] - ph;
        }

        // ---- channel 1 ----
        loadwin<O>(f1 + gy1 * WW, gxb, safe, t);
        loadwin<O>(f1 + gy2 * WW, gxb, safe, u);
        #pragma unroll
        for (int j = 0; j < 4; j++) {
            const float ph = w11 * t[j] + w12 * t[j + 1]
                           + w21 * u[j] + w22 * u[j + 1];
            const float d1 = c1a[j] - ph;
            const float s  = d1 * sb0 - d0[j] * sb1;
            acc[j] = fmaf(mm[j] * s, s, acc[j]);
        }
    }
    return (acc[0] + acc[1]) + (acc[2] + acc[3]);
}

__global__ __launch_bounds__(256, 6) void symloss_kernel(
    const float* __restrict__ Flow,
    const float* __restrict__ Asym,
    const float* __restrict__ Bsym,
    const float* __restrict__ Mask,
    float* __restrict__ out)
{
    const int b    = blockIdx.y;
    const int row0 = blockIdx.x * 8;

    const float a0  = __ldg(Asym + 2 * b);
    const float a1  = __ldg(Asym + 2 * b + 1);
    const float sb0 = __ldg(Bsym + 2 * b);
    const float sb1 = __ldg(Bsym + 2 * b + 1);

    const float dxf = -3.0f * a0;
    const float dyf = fabsf(3.0f * a1);
    const float dy1 = floorf(dyf);
    const float dx1 = floorf(dxf);
    const float fy  = dyf - dy1;
    const float fx  = dxf - dx1;
    const int   iy1 = (int)dy1;          // >= 0
    const int   ix1 = (int)dx1;          // may be negative

    const int hp   = HH - 1 - iy1;
    const int x_lo = max(0, -ix1);
    const int x_hi = min(WW, WW - 1 - ix1);

    const float w11 = (1.0f - fx) * (1.0f - fy);
    const float w12 = fx * (1.0f - fy);
    const float w21 = (1.0f - fx) * fy;
    const float w22 = fx * fy;

    const float* f0  = Flow + (size_t)b * 2 * HH * WW;
    const float* f1  = f0 + HH * WW;
    const float* m0p = Mask + (size_t)b * 2 * HH * WW;
    const float* m1p = m0p + HH * WW;

    // 128 x-groups (4 px each) x 2 y-halves; each thread walks 4 consecutive rows
    const int x0 = (threadIdx.x & 127) * 4;
    const int y0 = row0 + (threadIdx.x >> 7) * 4;

    const int  o    = ix1 & 3;                 // block-uniform misalignment
    const int  gxb  = x0 + (ix1 & ~3);         // 16B-aligned window base
    const bool safe = (gxb >= 0) && (gxb + 8 <= WW);

    float acc;
    switch (o) {                               // block-uniform branch
    case 0: acc = sym_body<0>(f0, f1, m0p, m1p, y0, x0, gxb, safe,
                              iy1, hp, x_lo, x_hi, w11, w12, w21, w22, sb0, sb1); break;
    case 1: acc = sym_body<1>(f0, f1, m0p, m1p, y0, x0, gxb, safe,
                              iy1, hp, x_lo, x_hi, w11, w12, w21, w22, sb0, sb1); break;
    case 2: acc = sym_body<2>(f0, f1, m0p, m1p, y0, x0, gxb, safe,
                              iy1, hp, x_lo, x_hi, w11, w12, w21, w22, sb0, sb1); break;
    default: acc = sym_body<3>(f0, f1, m0p, m1p, y0, x0, gxb, safe,
                              iy1, hp, x_lo, x_hi, w11, w12, w21, w22, sb0, sb1); break;
    }

    // ---- reduction: warp shuffle -> shared -> one atomic per block ----
    #pragma unroll
    for (int off = 16; off; off >>= 1)
        acc += __shfl_xor_sync(0xffffffffu, acc, off);

    __shared__ float sred[8];
    const int wid = threadIdx.x >> 5;
    const int lid = threadIdx.x & 31;
    if (lid == 0) sred[wid] = acc;
    __syncthreads();

    if (threadIdx.x == 0) {
        float s = 0.0f;
        #pragma unroll
        for (int i = 0; i < 8; i++) s += sred[i];
        const float denom = 2.0f * (float)max(hp, 1)
                          * (float)max(x_hi - x_lo, 1) * (float)BN;
        atomicAdd(out, s / denom);
    }
}

extern "C" void kernel_launch(void* const* d_in, const int* in_sizes, int n_in,
                              void* d_out, int out_size)
{
    const float* Flow = (const float*)d_in[0];
    const float* Asym = (const float*)d_in[1];
    const float* Bsym = (const float*)d_in[2];
    const float* Mask = (const float*)d_in[3];
    float* out = (float*)d_out;

    sym_zero_out<<<1, 1>>>(out);
    dim3 grid(HH / 8, BN);
    symloss_kernel<<<grid, 256>>>(Flow, Asym, Bsym, Mask, out);
}

// round 7
// speedup vs baseline: 1.2410x; 1.1819x over previous
#include <cuda_runtime.h>

// SymLoss: B=32, Flow/Mask (B,2,512,512) f32, A/B axes (B,2) f32.
// loss = (1/B) * sum_b num_b / denom_b
//   num_b = sum_{c,y,x} mask[c] * ((dphi1*b0 - dphi0*b1)^2) * valid
//   dphi  = flow - bilinear(flow shifted by (dy,dx))
//
// R7 = R4 (best: rolling window reuse, 4-row chains, branchless) + a one-row
// software pipeline on the mask/center streams (the cold-DRAM loads), at
// ~64 regs / 4 blocks/SM. Latency-bound kernel: batching depth >> occupancy.

#define HH 512
#define WW 512
#define BN 32

__global__ void sym_zero_out(float* out) { out[0] = 0.0f; }

// Load the aligned 8-float window, keep only the 5 consumed floats [O..O+4].
template <int O>
__device__ __forceinline__ void loadwin(const float* __restrict__ rowp,
                                        int gxb, bool safe, float* w)
{
    if (safe) {
        const float4 a = __ldg(reinterpret_cast<const float4*>(rowp + gxb));
        const float4 b = __ldg(reinterpret_cast<const float4*>(rowp + gxb + 4));
        const float w8[8] = {a.x, a.y, a.z, a.w, b.x, b.y, b.z, b.w};
        #pragma unroll
        for (int i = 0; i < 5; i++) w[i] = w8[O + i];
    } else {
        #pragma unroll
        for (int i = 0; i < 5; i++) {
            const int gx = min(max(gxb + O + i, 0), WW - 1);
            w[i] = __ldg(rowp + gx);
        }
    }
}

template <int O>
__device__ __forceinline__ float sym_body(
    const float* __restrict__ f0, const float* __restrict__ f1,
    const float* __restrict__ m0p, const float* __restrict__ m1p,
    int y0, int x0, int gxb, bool safe,
    int iy1, int hp, int x_lo, int x_hi,
    float w11, float w12, float w21, float w22, float sb0, float sb1)
{
    // x-validity is row-independent.
    float xm[4];
    #pragma unroll
    for (int j = 0; j < 4; j++) {
        const int xx = x0 + j;
        xm[j] = (xx >= x_lo && xx < x_hi) ? 1.0f : 0.0f;
    }

    float acc[4] = {0.0f, 0.0f, 0.0f, 0.0f};

    float t0[5], t1[5], u0[5], u1[5];
    {
        const int gy = min(y0 + iy1, HH - 1);
        loadwin<O>(f0 + gy * WW, gxb, safe, t0);
        loadwin<O>(f1 + gy * WW, gxb, safe, t1);
    }

    // prefetch row 0's DRAM streams (mask + center)
    float4 q0 = __ldg(reinterpret_cast<const float4*>(m0p + y0 * WW + x0));
    float4 q1 = __ldg(reinterpret_cast<const float4*>(m1p + y0 * WW + x0));
    float4 c0 = __ldg(reinterpret_cast<const float4*>(f0  + y0 * WW + x0));
    float4 c1 = __ldg(reinterpret_cast<const float4*>(f1  + y0 * WW + x0));

    #pragma unroll
    for (int r = 0; r < 4; r++) {
        const int y   = y0 + r;
        const int gy2 = min(y + iy1 + 1, HH - 1);
        const float yv = (y < hp) ? 1.0f : 0.0f;

        loadwin<O>(f0 + gy2 * WW, gxb, safe, u0);
        loadwin<O>(f1 + gy2 * WW, gxb, safe, u1);

        // consume current streams, then immediately issue next row's
        const float4 P0 = q0, P1 = q1, C0 = c0, C1 = c1;
        if (r < 3) {
            const int yn = y + 1;
            q0 = __ldg(reinterpret_cast<const float4*>(m0p + yn * WW + x0));
            q1 = __ldg(reinterpret_cast<const float4*>(m1p + yn * WW + x0));
            c0 = __ldg(reinterpret_cast<const float4*>(f0  + yn * WW + x0));
            c1 = __ldg(reinterpret_cast<const float4*>(f1  + yn * WW + x0));
        }

        const float mm[4]  = {(P0.x + P1.x) * xm[0] * yv, (P0.y + P1.y) * xm[1] * yv,
                              (P0.z + P1.z) * xm[2] * yv, (P0.w + P1.w) * xm[3] * yv};
        const float c0a[4] = {C0.x, C0.y, C0.z, C0.w};
        const float c1a[4] = {C1.x, C1.y, C1.z, C1.w};

        #pragma unroll
        for (int j = 0; j < 4; j++) {
            const float ph0 = w11 * t0[j] + w12 * t0[j + 1]
                            + w21 * u0[j] + w22 * u0[j + 1];
            const float ph1 = w11 * t1[j] + w12 * t1[j + 1]
                            + w21 * u1[j] + w22 * u1[j + 1];
            const float d0 = c0a[j] - ph0;
            const float d1 = c1a[j] - ph1;
            const float s  = d1 * sb0 - d0 * sb1;
            acc[j] = fmaf(mm[j] * s, s, acc[j]);
        }

        #pragma unroll
        for (int i = 0; i < 5; i++) { t0[i] = u0[i]; t1[i] = u1[i]; }
    }
    return (acc[0] + acc[1]) + (acc[2] + acc[3]);
}

__global__ __launch_bounds__(256, 4) void symloss_kernel(
    const float* __restrict__ Flow,
    const float* __restrict__ Asym,
    const float* __restrict__ Bsym,
    const float* __restrict__ Mask,
    float* __restrict__ out)
{
    const int b    = blockIdx.y;
    const int row0 = blockIdx.x * 8;

    const float a0  = __ldg(Asym + 2 * b);
    const float a1  = __ldg(Asym + 2 * b + 1);
    const float sb0 = __ldg(Bsym + 2 * b);
    const float sb1 = __ldg(Bsym + 2 * b + 1);

    const float dxf = -3.0f * a0;
    const float dyf = fabsf(3.0f * a1);
    const float dy1 = floorf(dyf);
    const float dx1 = floorf(dxf);
    const float fy  = dyf - dy1;
    const float fx  = dxf - dx1;
    const int   iy1 = (int)dy1;          // >= 0
    const int   ix1 = (int)dx1;          // may be negative

    const int hp   = HH - 1 - iy1;
    const int x_lo = max(0, -ix1);
    const int x_hi = min(WW, WW - 1 - ix1);

    const float w11 = (1.0f - fx) * (1.0f - fy);
    const float w12 = fx * (1.0f - fy);
    const float w21 = (1.0f - fx) * fy;
    const float w22 = fx * fy;

    const float* f0  = Flow + (size_t)b * 2 * HH * WW;
    const float* f1  = f0 + HH * WW;
    const float* m0p = Mask + (size_t)b * 2 * HH * WW;
    const float* m1p = m0p + HH * WW;

    // 128 x-groups (4 px each) x 2 y-halves; each thread walks 4 consecutive rows
    const int x0 = (threadIdx.x & 127) * 4;
    const int y0 = row0 + (threadIdx.x >> 7) * 4;

    const int  o    = ix1 & 3;                 // block-uniform misalignment
    const int  gxb  = x0 + (ix1 & ~3);         // 16B-aligned window base
    const bool safe = (gxb >= 0) && (gxb + 8 <= WW);

    float acc;
    switch (o) {                               // block-uniform branch
    case 0: acc = sym_body<0>(f0, f1, m0p, m1p, y0, x0, gxb, safe,
                              iy1, hp, x_lo, x_hi, w11, w12, w21, w22, sb0, sb1); break;
    case 1: acc = sym_body<1>(f0, f1, m0p, m1p, y0, x0, gxb, safe,
                              iy1, hp, x_lo, x_hi, w11, w12, w21, w22, sb0, sb1); break;
    case 2: acc = sym_body<2>(f0, f1, m0p, m1p, y0, x0, gxb, safe,
                              iy1, hp, x_lo, x_hi, w11, w12, w21, w22, sb0, sb1); break;
    default: acc = sym_body<3>(f0, f1, m0p, m1p, y0, x0, gxb, safe,
                              iy1, hp, x_lo, x_hi, w11, w12, w21, w22, sb0, sb1); break;
    }

    // ---- reduction: warp shuffle -> shared -> one atomic per block ----
    #pragma unroll
    for (int off = 16; off; off >>= 1)
        acc += __shfl_xor_sync(0xffffffffu, acc, off);

    __shared__ float sred[8];
    const int wid = threadIdx.x >> 5;
    const int lid = threadIdx.x & 31;
    if (lid == 0) sred[wid] = acc;
    __syncthreads();

    if (threadIdx.x == 0) {
        float s = 0.0f;
        #pragma unroll
        for (int i = 0; i < 8; i++) s += sred[i];
        const float denom = 2.0f * (float)max(hp, 1)
                          * (float)max(x_hi - x_lo, 1) * (float)BN;
        atomicAdd(out, s / denom);
    }
}

extern "C" void kernel_launch(void* const* d_in, const int* in_sizes, int n_in,
                              void* d_out, int out_size)
{
    const float* Flow = (const float*)d_in[0];
    const float* Asym = (const float*)d_in[1];
    const float* Bsym = (const float*)d_in[2];
    const float* Mask = (const float*)d_in[3];
    float* out = (float*)d_out;

    sym_zero_out<<<1, 1>>>(out);
    dim3 grid(HH / 8, BN);
    symloss_kernel<<<grid, 256>>>(Flow, Asym, Bsym, Mask, out);
}